// round 3
// baseline (speedup 1.0000x reference)
#include <cuda_runtime.h>

#define NNODES 50000
#define FIN    128
#define DDIM   64
#define HDIM   128
#define BGRAPH 16
#define E1N    800000
#define E2N    200000
#define AREG   2000
#define SLOTS  2048

typedef unsigned long long ull;

// ---------------- f32x2 helpers --------------------------------------------------
__device__ __forceinline__ ull ffma2(ull a, ull b, ull c) {
    ull d;
    asm("fma.rn.f32x2 %0, %1, %2, %3;" : "=l"(d) : "l"(a), "l"(b), "l"(c));
    return d;
}
__device__ __forceinline__ ull pack2(float lo, float hi) {
    ull r;
    asm("mov.b64 %0, {%1, %2};" : "=l"(r) : "f"(lo), "f"(hi));
    return r;
}
__device__ __forceinline__ void unpack2(ull v, float& lo, float& hi) {
    asm("mov.b64 {%0, %1}, %2;" : "=f"(lo), "=f"(hi) : "l"(v));
}

// ---------------- scratch (device globals; no allocation allowed) ----------------
__device__ __align__(16) float d_yl[NNODES * DDIM];     // x @ W1l
__device__ __align__(16) float d_yr[NNODES * DDIM];     // x @ W1r + b1
__device__ __align__(16) float d_h1[NNODES * DDIM];     // relu(mean + yr)
__device__ __align__(16) float d_gl[NNODES * DDIM];     // h1 @ W2l
__device__ __align__(16) float d_gr[NNODES * DDIM];     // h1 @ W2r + b2
__device__ __align__(16) int   d_cnt[NNODES];           // conv1 in-degree
__device__ __align__(16) int   d_off[NNODES];           // CSR exclusive offsets
__device__ __align__(16) int   d_fill[NNODES];          // bucket cursors
__device__ __align__(16) int   d_csr[E1N];              // CSR src ids (by dst)
__device__ __align__(16) int   d_slotmap[BGRAPH * NNODES];
__device__ __align__(16) int   d_counter[BGRAPH];
__device__ __align__(16) float d_acc2[BGRAPH * SLOTS * DDIM];
__device__ __align__(16) float d_deg2[BGRAPH * SLOTS];
__device__ __align__(16) float d_h2[BGRAPH * SLOTS * DDIM];
__device__ __align__(16) float d_u[BGRAPH * HDIM];      // Wo @ target_embed
__device__ __align__(16) float d_c[BGRAPH];             // bo . target_embed

// ---------------- clear kernel ---------------------------------------------------
static constexpr int CLR_ACC2 = BGRAPH * SLOTS * DDIM / 4;  // 524288 float4
static constexpr int CLR_SMAP = BGRAPH * NNODES / 4;        // 200000 int4 (-1)
static constexpr int CLR_DEG2 = BGRAPH * SLOTS / 4;         // 8192
static constexpr int CLR_CNT1 = NNODES / 4;                 // 12500 int4
static constexpr int CLR_CNT  = BGRAPH / 4;                 // 4
static constexpr int CLR_TOTAL = CLR_ACC2 + CLR_SMAP + CLR_DEG2 + CLR_CNT1 + CLR_CNT;

__global__ void clear_kernel() {
    int i = blockIdx.x * blockDim.x + threadIdx.x;
    float4 z = make_float4(0.f, 0.f, 0.f, 0.f);
    if (i < CLR_ACC2) { ((float4*)d_acc2)[i] = z; return; }
    i -= CLR_ACC2;
    if (i < CLR_SMAP) { ((int4*)d_slotmap)[i] = make_int4(-1, -1, -1, -1); return; }
    i -= CLR_SMAP;
    if (i < CLR_DEG2) { ((float4*)d_deg2)[i] = z; return; }
    i -= CLR_DEG2;
    if (i < CLR_CNT1) { ((int4*)d_cnt)[i] = make_int4(0, 0, 0, 0); return; }
    i -= CLR_CNT1;
    if (i < CLR_CNT)  { ((int4*)d_counter)[i] = make_int4(0, 0, 0, 0); }
}

// ---------------- CSR build: histogram -> scan -> fill ---------------------------
__global__ void hist_kernel(const int* __restrict__ ei) {
    int idx = (blockIdx.x * blockDim.x + threadIdx.x) * 4;
    if (idx >= E1N) return;
    int4 d = *(const int4*)(ei + E1N + idx);
    atomicAdd(&d_cnt[d.x], 1);
    atomicAdd(&d_cnt[d.y], 1);
    atomicAdd(&d_cnt[d.z], 1);
    atomicAdd(&d_cnt[d.w], 1);
}

__global__ void scan_kernel() {
    // single block, 1024 threads; chunked serial + block scan
    __shared__ int part[1024];
    const int t = threadIdx.x;
    const int CH = (NNODES + 1023) / 1024;   // 49
    int lo = t * CH, hi = min(lo + CH, NNODES);
    int s = 0;
    for (int n = lo; n < hi; n++) s += d_cnt[n];
    part[t] = s;
    __syncthreads();
    // Hillis-Steele inclusive scan
    for (int o = 1; o < 1024; o <<= 1) {
        int v = (t >= o) ? part[t - o] : 0;
        __syncthreads();
        part[t] += v;
        __syncthreads();
    }
    int run = part[t] - s;   // exclusive base
    for (int n = lo; n < hi; n++) {
        d_off[n] = run;
        d_fill[n] = run;
        run += d_cnt[n];
    }
}

__global__ void fill_kernel(const int* __restrict__ ei) {
    int idx = (blockIdx.x * blockDim.x + threadIdx.x) * 4;
    if (idx >= E1N) return;
    int4 s = *(const int4*)(ei + idx);
    int4 d = *(const int4*)(ei + E1N + idx);
    d_csr[atomicAdd(&d_fill[d.x], 1)] = s.x;
    d_csr[atomicAdd(&d_fill[d.y], 1)] = s.y;
    d_csr[atomicAdd(&d_fill[d.z], 1)] = s.z;
    d_csr[atomicAdd(&d_fill[d.w], 1)] = s.w;
}

// ---------------- conv1 gather: h1 = relu(mean_{src} yl[src] + yr) ---------------
// one half-warp (16 lanes) per node; 4-deep unroll for MLP
__global__ void gather1_kernel() {
    int tid = blockIdx.x * blockDim.x + threadIdx.x;
    int w = tid >> 5, lane = tid & 31;
    int node = 2 * w + (lane >> 4);
    if (node >= NNODES) return;
    int j = lane & 15;
    int off = d_off[node];
    int deg = d_cnt[node];
    float4 acc = make_float4(0.f, 0.f, 0.f, 0.f);
    int i = 0;
    for (; i + 4 <= deg; i += 4) {
        int s0 = __ldg(d_csr + off + i);
        int s1 = __ldg(d_csr + off + i + 1);
        int s2 = __ldg(d_csr + off + i + 2);
        int s3 = __ldg(d_csr + off + i + 3);
        float4 v0 = ((const float4*)(d_yl + s0 * 64))[j];
        float4 v1 = ((const float4*)(d_yl + s1 * 64))[j];
        float4 v2 = ((const float4*)(d_yl + s2 * 64))[j];
        float4 v3 = ((const float4*)(d_yl + s3 * 64))[j];
        acc.x += v0.x + v1.x + v2.x + v3.x;
        acc.y += v0.y + v1.y + v2.y + v3.y;
        acc.z += v0.z + v1.z + v2.z + v3.z;
        acc.w += v0.w + v1.w + v2.w + v3.w;
    }
    for (; i < deg; i++) {
        int s = __ldg(d_csr + off + i);
        float4 v = ((const float4*)(d_yl + s * 64))[j];
        acc.x += v.x; acc.y += v.y; acc.z += v.z; acc.w += v.w;
    }
    float inv = 1.f / fmaxf((float)deg, 1.f);
    float4 y = ((const float4*)(d_yr + node * 64))[j];
    float4 h;
    h.x = fmaxf(acc.x * inv + y.x, 0.f);
    h.y = fmaxf(acc.y * inv + y.y, 0.f);
    h.z = fmaxf(acc.z * inv + y.z, 0.f);
    h.w = fmaxf(acc.w * inv + y.w, 0.f);
    ((float4*)(d_h1 + node * 64))[j] = h;
}

// ---------------- dual GEMM (f32x2 packed): C1 = A@W1, C2 = A@W2 + bias ---------
template <int K>
__global__ void dual_gemm_kernel(const float* __restrict__ A,
                                 const float* __restrict__ W1,
                                 const float* __restrict__ W2,
                                 const float* __restrict__ bias,
                                 float* __restrict__ C1,
                                 float* __restrict__ C2,
                                 int nrows) {
    __shared__ float sA[32][66];
    __shared__ float sW1[32][64];
    __shared__ float sW2[32][64];

    const int t = threadIdx.x;
    const int tx = t & 63;
    const int ty = t >> 6;
    const int row0 = blockIdx.x * 64;

    ull acc1[8], acc2[8];
#pragma unroll
    for (int i = 0; i < 8; i++) { acc1[i] = 0ull; acc2[i] = 0ull; }

    for (int k0 = 0; k0 < K; k0 += 32) {
#pragma unroll
        for (int i = 0; i < 8; i++) {
            int idx = t + i * 256;
            int r = idx >> 5, kk = idx & 31;
            int row = row0 + r;
            sA[kk][r] = (row < nrows) ? A[row * K + k0 + kk] : 0.f;
        }
#pragma unroll
        for (int i = 0; i < 8; i++) {
            int idx = t + i * 256;
            int kk = idx >> 6, c = idx & 63;
            sW1[kk][c] = W1[(k0 + kk) * 64 + c];
            sW2[kk][c] = W2[(k0 + kk) * 64 + c];
        }
        __syncthreads();
#pragma unroll
        for (int kk = 0; kk < 32; kk++) {
            ull w1 = pack2(sW1[kk][tx], sW1[kk][tx]);
            ull w2 = pack2(sW2[kk][tx], sW2[kk][tx]);
            const ull* ap = (const ull*)&sA[kk][ty * 16];
#pragma unroll
            for (int u = 0; u < 8; u++) {
                ull av = ap[u];
                acc1[u] = ffma2(av, w1, acc1[u]);
                acc2[u] = ffma2(av, w2, acc2[u]);
            }
        }
        __syncthreads();
    }
    float bb = bias[tx];
#pragma unroll
    for (int u = 0; u < 8; u++) {
        float l1, h1v, l2, h2v;
        unpack2(acc1[u], l1, h1v);
        unpack2(acc2[u], l2, h2v);
        int row = row0 + ty * 16 + 2 * u;
        if (row < nrows) {
            C1[row * 64 + tx] = l1;
            C2[row * 64 + tx] = l2 + bb;
        }
        if (row + 1 < nrows) {
            C1[(row + 1) * 64 + tx] = h1v;
            C2[(row + 1) * 64 + tx] = h2v + bb;
        }
    }
}

// ---------------- per-graph needed-node slot assignment -------------------------
__global__ void slot_kernel(const int* __restrict__ targets,
                            const int* __restrict__ regions) {
    int idx = blockIdx.x * blockDim.x + threadIdx.x;
    if (idx >= BGRAPH * (AREG + 1)) return;
    int b = idx / (AREG + 1);
    int j = idx % (AREG + 1);
    int node = (j == AREG) ? targets[b] : regions[b * AREG + j];
    int* p = &d_slotmap[b * NNODES + node];
    if (atomicCAS(p, -1, -2) == -1) {
        int s = atomicAdd(&d_counter[b], 1);
        atomicExch(p, s);
    }
}

// ---------------- conv2 edge scatter (only needed destinations) -----------------
__global__ void scatter2_kernel(const int* __restrict__ ne) {
    int idx = blockIdx.x * blockDim.x + threadIdx.x;
    int lane = threadIdx.x & 31;
    int b = idx / E2N;                  // uniform per warp (E2N % 32 == 0)
    int e = idx - b * E2N;
    int slot = -1, src = 0;
    int dst = ne[b * 2 * E2N + E2N + e];
    slot = d_slotmap[b * NNODES + dst];
    if (slot >= 0) src = ne[b * 2 * E2N + e];
    unsigned mask = __ballot_sync(0xffffffffu, slot >= 0);
    while (mask) {
        int bit = __ffs(mask) - 1;
        mask &= mask - 1;
        int es = __shfl_sync(0xffffffffu, src, bit);
        int sl = __shfl_sync(0xffffffffu, slot, bit);
        float2 v = ((const float2*)(d_gl + es * 64))[lane];
        float* p = d_acc2 + (b * SLOTS + sl) * 64 + 2 * lane;
        asm volatile("red.global.add.v2.f32 [%0], {%1,%2};"
                     :: "l"(p), "f"(v.x), "f"(v.y) : "memory");
        if (lane == 0) atomicAdd(&d_deg2[b * SLOTS + sl], 1.0f);
    }
}

// ---------------- h2 at needed slots: relu(acc2/deg + gr) -----------------------
__global__ void h2_kernel(const int* __restrict__ targets,
                          const int* __restrict__ regions) {
    int tid = blockIdx.x * blockDim.x + threadIdx.x;
    int w = tid >> 5, lane = tid & 31;
    if (w >= BGRAPH * (AREG + 1)) return;
    int b = w / (AREG + 1);
    int j = w % (AREG + 1);
    int node = (j == AREG) ? targets[b] : regions[b * AREG + j];
    int s = d_slotmap[b * NNODES + node];
    int base = (b * SLOTS + s) * 64;
    float inv = 1.f / fmaxf(d_deg2[b * SLOTS + s], 1.f);
    float2 a = ((const float2*)(d_acc2 + base))[lane];
    float2 g = ((const float2*)(d_gr + node * 64))[lane];
    float2 h;
    h.x = fmaxf(a.x * inv + g.x, 0.f);
    h.y = fmaxf(a.y * inv + g.y, 0.f);
    ((float2*)(d_h2 + base))[lane] = h;
}

// ---------------- u_b = Wo @ t_b , c_b = bo . t_b -------------------------------
__global__ void u_kernel(const int* __restrict__ targets,
                         const float* __restrict__ Wo,
                         const float* __restrict__ bo) {
    int idx = blockIdx.x * blockDim.x + threadIdx.x;
    if (idx >= BGRAPH * HDIM) return;
    int b = idx / HDIM;
    int h = idx % HDIM;
    int node = targets[b];
    int s = d_slotmap[b * NNODES + node];
    const float* t = d_h2 + (b * SLOTS + s) * 64;
    float acc = 0.f;
#pragma unroll
    for (int d = 0; d < 64; d++) acc += Wo[h * 64 + d] * t[d];
    d_u[idx] = acc;
    if (h == 0) {
        float c = 0.f;
#pragma unroll
        for (int d = 0; d < 64; d++) c += bo[d] * t[d];
        d_c[b] = c;
    }
}

// ---------------- final readout: q[p] = relu(reg@Wm+bm).u_b + c_b ---------------
__global__ void final_kernel(const int* __restrict__ regions,
                             const float* __restrict__ Wm,
                             const float* __restrict__ bm,
                             float* __restrict__ q) {
    __shared__ float sWm[64 * 128];   // 32 KB
    __shared__ float sreg[8][8][64];  // 16 KB
    for (int i = threadIdx.x; i < 64 * 128; i += blockDim.x)
        sWm[i] = Wm[i];
    __syncthreads();

    const int lane = threadIdx.x & 31;
    const int wl = threadIdx.x >> 5;
    const float2 bmp0 = ((const float2*)bm)[lane];
    const float2 bmp1 = ((const float2*)bm)[lane + 32];

    for (int tile = blockIdx.x * 8 + wl; tile < 4000; tile += gridDim.x * 8) {
        int b = tile / 250;
#pragma unroll
        for (int r = 0; r < 8; r++) {
            int p = tile * 8 + r;
            int node = regions[p];
            int s = d_slotmap[b * NNODES + node];
            float2 rv = ((const float2*)(d_h2 + (b * SLOTS + s) * 64))[lane];
            sreg[wl][r][2 * lane] = rv.x;
            sreg[wl][r][2 * lane + 1] = rv.y;
        }
        __syncwarp();

        ull acc0[8], acc1[8];
#pragma unroll
        for (int r = 0; r < 8; r++) { acc0[r] = 0ull; acc1[r] = 0ull; }

#pragma unroll 8
        for (int d = 0; d < 64; d++) {
            ull w0 = ((const ull*)(sWm + d * 128))[lane];
            ull w1 = ((const ull*)(sWm + d * 128 + 64))[lane];
#pragma unroll
            for (int r = 0; r < 8; r++) {
                float rd = sreg[wl][r][d];
                ull rdp = pack2(rd, rd);
                acc0[r] = ffma2(rdp, w0, acc0[r]);
                acc1[r] = ffma2(rdp, w1, acc1[r]);
            }
        }

        const float2* ubp = (const float2*)(d_u + b * HDIM);
        float2 u0 = ubp[lane];
        float2 u1 = ubp[lane + 32];
        float cb = d_c[b];
#pragma unroll
        for (int r = 0; r < 8; r++) {
            float m0, m1, m2, m3;
            unpack2(acc0[r], m0, m1);
            unpack2(acc1[r], m2, m3);
            float sum = fmaxf(m0 + bmp0.x, 0.f) * u0.x
                      + fmaxf(m1 + bmp0.y, 0.f) * u0.y
                      + fmaxf(m2 + bmp1.x, 0.f) * u1.x
                      + fmaxf(m3 + bmp1.y, 0.f) * u1.y;
#pragma unroll
            for (int o = 16; o > 0; o >>= 1)
                sum += __shfl_down_sync(0xffffffffu, sum, o);
            if (lane == 0) q[tile * 8 + r] = sum + cb;
        }
        __syncwarp();
    }
}

// ---------------- launch ---------------------------------------------------------
extern "C" void kernel_launch(void* const* d_in, const int* in_sizes, int n_in,
                              void* d_out, int out_size) {
    const float* x       = (const float*)d_in[0];
    const int*   ei      = (const int*)  d_in[1];
    const int*   ne      = (const int*)  d_in[2];
    const int*   targets = (const int*)  d_in[3];
    const int*   regions = (const int*)  d_in[4];
    const float* W1l     = (const float*)d_in[5];
    const float* W1r     = (const float*)d_in[6];
    const float* b1      = (const float*)d_in[7];
    const float* W2l     = (const float*)d_in[8];
    const float* W2r     = (const float*)d_in[9];
    const float* b2      = (const float*)d_in[10];
    const float* Wm      = (const float*)d_in[11];
    const float* bm      = (const float*)d_in[12];
    const float* Wo      = (const float*)d_in[13];
    const float* bo      = (const float*)d_in[14];
    float* q = (float*)d_out;

    float *p_yl, *p_yr, *p_h1, *p_gl, *p_gr;
    cudaGetSymbolAddress((void**)&p_yl, d_yl);
    cudaGetSymbolAddress((void**)&p_yr, d_yr);
    cudaGetSymbolAddress((void**)&p_h1, d_h1);
    cudaGetSymbolAddress((void**)&p_gl, d_gl);
    cudaGetSymbolAddress((void**)&p_gr, d_gr);

    // 1. clear scratch (acc2, slotmap, deg2, cnt, counters)
    clear_kernel<<<(CLR_TOTAL + 255) / 256, 256>>>();

    // 2. CSR build for conv1
    hist_kernel<<<(E1N / 4 + 255) / 256, 256>>>(ei);
    scan_kernel<<<1, 1024>>>();
    fill_kernel<<<(E1N / 4 + 255) / 256, 256>>>(ei);

    // 3. yl = x@W1l ; yr = x@W1r + b1
    dual_gemm_kernel<FIN><<<(NNODES + 63) / 64, 256>>>(x, W1l, W1r, b1, p_yl, p_yr, NNODES);

    // 4. conv1 gather -> h1
    gather1_kernel<<<(NNODES / 2 * 32 + 255) / 256, 256>>>();

    // 5. gl = h1@W2l ; gr = h1@W2r + b2
    dual_gemm_kernel<DDIM><<<(NNODES + 63) / 64, 256>>>(p_h1, W2l, W2r, b2, p_gl, p_gr, NNODES);

    // 6. slot assignment
    slot_kernel<<<(BGRAPH * (AREG + 1) + 255) / 256, 256>>>(targets, regions);

    // 7. conv2 scatter, needed dsts only
    scatter2_kernel<<<(BGRAPH * E2N) / 256, 256>>>(ne);

    // 8. h2 at needed slots
    {
        int warps = BGRAPH * (AREG + 1);
        h2_kernel<<<(warps * 32 + 255) / 256, 256>>>(targets, regions);
    }

    // 9. u_b = Wo @ t_b, c_b
    u_kernel<<<(BGRAPH * HDIM + 255) / 256, 256>>>(targets, Wo, bo);

    // 10. readout
    final_kernel<<<250, 256>>>(regions, Wm, bm, q);
}

// round 4
// speedup vs baseline: 1.2327x; 1.2327x over previous
#include <cuda_runtime.h>

#define NNODES 50000
#define FIN    128
#define DDIM   64
#define HDIM   128
#define BGRAPH 16
#define E1N    800000
#define E2N    200000
#define AREG   2000
#define SLOTS  2048

typedef unsigned long long ull;

// ---------------- f32x2 helpers --------------------------------------------------
__device__ __forceinline__ ull ffma2(ull a, ull b, ull c) {
    ull d;
    asm("fma.rn.f32x2 %0, %1, %2, %3;" : "=l"(d) : "l"(a), "l"(b), "l"(c));
    return d;
}
__device__ __forceinline__ ull pack2(float lo, float hi) {
    ull r;
    asm("mov.b64 %0, {%1, %2};" : "=l"(r) : "f"(lo), "f"(hi));
    return r;
}
__device__ __forceinline__ void unpack2(ull v, float& lo, float& hi) {
    asm("mov.b64 {%0, %1}, %2;" : "=f"(lo), "=f"(hi) : "l"(v));
}

// ---------------- scratch (device globals; no allocation allowed) ----------------
__device__ __align__(16) float d_yl[NNODES * DDIM];     // x @ W1l
__device__ __align__(16) float d_yr[NNODES * DDIM];     // x @ W1r + b1
__device__ __align__(16) float d_agg1[NNODES * DDIM];   // conv1 neighbor sum of yl
__device__ __align__(16) float d_deg1[NNODES];
__device__ __align__(16) float d_gl[NNODES * DDIM];     // h1 @ W2l
__device__ __align__(16) float d_gr[NNODES * DDIM];     // h1 @ W2r + b2
__device__ __align__(16) int   d_slotmap[BGRAPH * NNODES];
__device__ __align__(16) int   d_counter[BGRAPH];
__device__ __align__(16) float d_acc2[BGRAPH * SLOTS * DDIM];
__device__ __align__(16) float d_deg2[BGRAPH * SLOTS];
__device__ __align__(16) float d_h2[BGRAPH * SLOTS * DDIM];
__device__ __align__(16) float d_u[BGRAPH * HDIM];      // Wo @ target_embed
__device__ __align__(16) float d_c[BGRAPH];             // bo . target_embed

// ---------------- clear kernel ---------------------------------------------------
static constexpr int CLR_AGG1 = NNODES * DDIM / 4;
static constexpr int CLR_ACC2 = BGRAPH * SLOTS * DDIM / 4;
static constexpr int CLR_SMAP = BGRAPH * NNODES / 4;
static constexpr int CLR_DEG1 = NNODES / 4;
static constexpr int CLR_DEG2 = BGRAPH * SLOTS / 4;
static constexpr int CLR_CNT  = BGRAPH / 4;
static constexpr int CLR_TOTAL = CLR_AGG1 + CLR_ACC2 + CLR_SMAP + CLR_DEG1 + CLR_DEG2 + CLR_CNT;

__global__ void clear_kernel() {
    int i = blockIdx.x * blockDim.x + threadIdx.x;
    float4 z = make_float4(0.f, 0.f, 0.f, 0.f);
    if (i < CLR_AGG1) { ((float4*)d_agg1)[i] = z; return; }
    i -= CLR_AGG1;
    if (i < CLR_ACC2) { ((float4*)d_acc2)[i] = z; return; }
    i -= CLR_ACC2;
    if (i < CLR_SMAP) { ((int4*)d_slotmap)[i] = make_int4(-1, -1, -1, -1); return; }
    i -= CLR_SMAP;
    if (i < CLR_DEG1) { ((float4*)d_deg1)[i] = z; return; }
    i -= CLR_DEG1;
    if (i < CLR_DEG2) { ((float4*)d_deg2)[i] = z; return; }
    i -= CLR_DEG2;
    if (i < CLR_CNT)  { ((int4*)d_counter)[i] = make_int4(0, 0, 0, 0); }
}

// ---------------- dual GEMM (f32x2 packed, pre-duplicated W) --------------------
// A [nrows, K] row-major, W [K, 64]. FUSE_H1: A row computed on the fly as
// relu(agg1/deg1 + yr).
template <int K, bool FUSE_H1>
__global__ void dual_gemm_kernel(const float* __restrict__ A,
                                 const float* __restrict__ W1,
                                 const float* __restrict__ W2,
                                 const float* __restrict__ bias,
                                 float* __restrict__ C1,
                                 float* __restrict__ C2,
                                 int nrows) {
    __shared__ float sA[32][66];      // row pairs 8B-aligned
    __shared__ float sW1[32][128];    // duplicated pairs: [kk][2c]=[kk][2c+1]=w
    __shared__ float sW2[32][128];

    const int t = threadIdx.x;
    const int tx = t & 63;          // output column
    const int ty = t >> 6;          // 0..3 -> rows ty*16 .. ty*16+15
    const int row0 = blockIdx.x * 64;

    ull acc1[8], acc2[8];
#pragma unroll
    for (int i = 0; i < 8; i++) { acc1[i] = 0ull; acc2[i] = 0ull; }

    for (int k0 = 0; k0 < K; k0 += 32) {
#pragma unroll
        for (int i = 0; i < 8; i++) {
            int idx = t + i * 256;       // 0..2047
            int r = idx >> 5, kk = idx & 31;
            int row = row0 + r;
            float v = 0.f;
            if (row < nrows) {
                if (FUSE_H1) {
                    float inv = 1.f / fmaxf(d_deg1[row], 1.f);
                    v = fmaxf(d_agg1[row * 64 + k0 + kk] * inv +
                              d_yr[row * 64 + k0 + kk], 0.f);
                } else {
                    v = A[row * K + k0 + kk];
                }
            }
            sA[kk][r] = v;
        }
#pragma unroll
        for (int i = 0; i < 8; i++) {
            int idx = t + i * 256;
            int kk = idx >> 6, c = idx & 63;
            float w1 = W1[(k0 + kk) * 64 + c];
            float w2 = W2[(k0 + kk) * 64 + c];
            sW1[kk][2 * c] = w1; sW1[kk][2 * c + 1] = w1;
            sW2[kk][2 * c] = w2; sW2[kk][2 * c + 1] = w2;
        }
        __syncthreads();
#pragma unroll
        for (int kk = 0; kk < 32; kk++) {
            ull w1 = ((const ull*)&sW1[kk][0])[tx];
            ull w2 = ((const ull*)&sW2[kk][0])[tx];
            const ull* ap = (const ull*)&sA[kk][ty * 16];
#pragma unroll
            for (int u = 0; u < 8; u++) {
                ull av = ap[u];
                acc1[u] = ffma2(av, w1, acc1[u]);
                acc2[u] = ffma2(av, w2, acc2[u]);
            }
        }
        __syncthreads();
    }
    float bb = bias[tx];
#pragma unroll
    for (int u = 0; u < 8; u++) {
        float l1, h1v, l2, h2v;
        unpack2(acc1[u], l1, h1v);
        unpack2(acc2[u], l2, h2v);
        int row = row0 + ty * 16 + 2 * u;
        if (row < nrows) {
            C1[row * 64 + tx] = l1;
            C2[row * 64 + tx] = l2 + bb;
        }
        if (row + 1 < nrows) {
            C1[(row + 1) * 64 + tx] = h1v;
            C2[(row + 1) * 64 + tx] = h2v + bb;
        }
    }
}

// ---------------- conv1 edge scatter: agg1[dst] += yl[src], deg1[dst]++ ---------
// 8 edges per warp: half-warp handles 4 edges, batched loads for MLP.
// E1N % 8 == 0 so no bounds checks needed.
__global__ void scatter1_kernel(const int* __restrict__ ei) {
    int tid = blockIdx.x * blockDim.x + threadIdx.x;
    int w = tid >> 5, lane = tid & 31;
    int e0 = 8 * w + (lane >> 4);       // this half-warp: e0, e0+2, e0+4, e0+6
    int j = lane & 15;

    int s0 = ei[e0];
    int s1 = ei[e0 + 2];
    int s2 = ei[e0 + 4];
    int s3 = ei[e0 + 6];
    int dd0 = ei[E1N + e0];
    int dd1 = ei[E1N + e0 + 2];
    int dd2 = ei[E1N + e0 + 4];
    int dd3 = ei[E1N + e0 + 6];

    float4 v0 = ((const float4*)(d_yl + s0 * 64))[j];
    float4 v1 = ((const float4*)(d_yl + s1 * 64))[j];
    float4 v2 = ((const float4*)(d_yl + s2 * 64))[j];
    float4 v3 = ((const float4*)(d_yl + s3 * 64))[j];

    float* p0 = d_agg1 + dd0 * 64 + 4 * j;
    float* p1 = d_agg1 + dd1 * 64 + 4 * j;
    float* p2 = d_agg1 + dd2 * 64 + 4 * j;
    float* p3 = d_agg1 + dd3 * 64 + 4 * j;
    asm volatile("red.global.add.v4.f32 [%0], {%1,%2,%3,%4};"
                 :: "l"(p0), "f"(v0.x), "f"(v0.y), "f"(v0.z), "f"(v0.w) : "memory");
    asm volatile("red.global.add.v4.f32 [%0], {%1,%2,%3,%4};"
                 :: "l"(p1), "f"(v1.x), "f"(v1.y), "f"(v1.z), "f"(v1.w) : "memory");
    asm volatile("red.global.add.v4.f32 [%0], {%1,%2,%3,%4};"
                 :: "l"(p2), "f"(v2.x), "f"(v2.y), "f"(v2.z), "f"(v2.w) : "memory");
    asm volatile("red.global.add.v4.f32 [%0], {%1,%2,%3,%4};"
                 :: "l"(p3), "f"(v3.x), "f"(v3.y), "f"(v3.z), "f"(v3.w) : "memory");
    if (j == 0) {
        atomicAdd(&d_deg1[dd0], 1.0f);
        atomicAdd(&d_deg1[dd1], 1.0f);
        atomicAdd(&d_deg1[dd2], 1.0f);
        atomicAdd(&d_deg1[dd3], 1.0f);
    }
}

// ---------------- per-graph needed-node slot assignment -------------------------
__global__ void slot_kernel(const int* __restrict__ targets,
                            const int* __restrict__ regions) {
    int idx = blockIdx.x * blockDim.x + threadIdx.x;
    if (idx >= BGRAPH * (AREG + 1)) return;
    int b = idx / (AREG + 1);
    int j = idx % (AREG + 1);
    int node = (j == AREG) ? targets[b] : regions[b * AREG + j];
    int* p = &d_slotmap[b * NNODES + node];
    if (atomicCAS(p, -1, -2) == -1) {
        int s = atomicAdd(&d_counter[b], 1);
        atomicExch(p, s);
    }
}

// ---------------- conv2 edge scatter (only needed destinations) -----------------
__global__ void scatter2_kernel(const int* __restrict__ ne) {
    int idx = blockIdx.x * blockDim.x + threadIdx.x;
    int lane = threadIdx.x & 31;
    int b = idx / E2N;                  // uniform per warp (E2N % 32 == 0)
    int e = idx - b * E2N;
    int slot = -1, src = 0;
    int dst = ne[b * 2 * E2N + E2N + e];
    slot = d_slotmap[b * NNODES + dst];
    if (slot >= 0) src = ne[b * 2 * E2N + e];
    unsigned mask = __ballot_sync(0xffffffffu, slot >= 0);
    while (mask) {
        int bit = __ffs(mask) - 1;
        mask &= mask - 1;
        int es = __shfl_sync(0xffffffffu, src, bit);
        int sl = __shfl_sync(0xffffffffu, slot, bit);
        float2 v = ((const float2*)(d_gl + es * 64))[lane];
        float* p = d_acc2 + (b * SLOTS + sl) * 64 + 2 * lane;
        asm volatile("red.global.add.v2.f32 [%0], {%1,%2};"
                     :: "l"(p), "f"(v.x), "f"(v.y) : "memory");
        if (lane == 0) atomicAdd(&d_deg2[b * SLOTS + sl], 1.0f);
    }
}

// ---------------- h2 at needed slots: relu(acc2/deg + gr) -----------------------
__global__ void h2_kernel(const int* __restrict__ targets,
                          const int* __restrict__ regions) {
    int tid = blockIdx.x * blockDim.x + threadIdx.x;
    int w = tid >> 5, lane = tid & 31;
    if (w >= BGRAPH * (AREG + 1)) return;
    int b = w / (AREG + 1);
    int j = w % (AREG + 1);
    int node = (j == AREG) ? targets[b] : regions[b * AREG + j];
    int s = d_slotmap[b * NNODES + node];
    int base = (b * SLOTS + s) * 64;
    float inv = 1.f / fmaxf(d_deg2[b * SLOTS + s], 1.f);
    float2 a = ((const float2*)(d_acc2 + base))[lane];
    float2 g = ((const float2*)(d_gr + node * 64))[lane];
    float2 h;
    h.x = fmaxf(a.x * inv + g.x, 0.f);
    h.y = fmaxf(a.y * inv + g.y, 0.f);
    ((float2*)(d_h2 + base))[lane] = h;
}

// ---------------- u_b = Wo @ t_b , c_b = bo . t_b -------------------------------
__global__ void u_kernel(const int* __restrict__ targets,
                         const float* __restrict__ Wo,
                         const float* __restrict__ bo) {
    int idx = blockIdx.x * blockDim.x + threadIdx.x;
    if (idx >= BGRAPH * HDIM) return;
    int b = idx / HDIM;
    int h = idx % HDIM;
    int node = targets[b];
    int s = d_slotmap[b * NNODES + node];
    const float* t = d_h2 + (b * SLOTS + s) * 64;
    float acc = 0.f;
#pragma unroll
    for (int d = 0; d < 64; d++) acc += Wo[h * 64 + d] * t[d];
    d_u[idx] = acc;
    if (h == 0) {
        float c = 0.f;
#pragma unroll
        for (int d = 0; d < 64; d++) c += bo[d] * t[d];
        d_c[b] = c;
    }
}

// ---------------- final readout: q[p] = relu(reg@Wm+bm).u_b + c_b ---------------
__global__ void final_kernel(const int* __restrict__ regions,
                             const float* __restrict__ Wm,
                             const float* __restrict__ bm,
                             float* __restrict__ q) {
    __shared__ float sWm[64 * 128];   // 32 KB
    __shared__ float sreg[8][8][64];  // 16 KB
    for (int i = threadIdx.x; i < 64 * 128; i += blockDim.x)
        sWm[i] = Wm[i];
    __syncthreads();

    const int lane = threadIdx.x & 31;
    const int wl = threadIdx.x >> 5;
    const float2 bmp0 = ((const float2*)bm)[lane];
    const float2 bmp1 = ((const float2*)bm)[lane + 32];

    for (int tile = blockIdx.x * 8 + wl; tile < 4000; tile += gridDim.x * 8) {
        int b = tile / 250;
#pragma unroll
        for (int r = 0; r < 8; r++) {
            int p = tile * 8 + r;
            int node = regions[p];
            int s = d_slotmap[b * NNODES + node];
            float2 rv = ((const float2*)(d_h2 + (b * SLOTS + s) * 64))[lane];
            sreg[wl][r][2 * lane] = rv.x;
            sreg[wl][r][2 * lane + 1] = rv.y;
        }
        __syncwarp();

        ull acc0[8], acc1[8];
#pragma unroll
        for (int r = 0; r < 8; r++) { acc0[r] = 0ull; acc1[r] = 0ull; }

#pragma unroll 8
        for (int d = 0; d < 64; d++) {
            ull w0 = ((const ull*)(sWm + d * 128))[lane];
            ull w1 = ((const ull*)(sWm + d * 128 + 64))[lane];
#pragma unroll
            for (int r = 0; r < 8; r++) {
                float rd = sreg[wl][r][d];
                ull rdp = pack2(rd, rd);
                acc0[r] = ffma2(rdp, w0, acc0[r]);
                acc1[r] = ffma2(rdp, w1, acc1[r]);
            }
        }

        const float2* ubp = (const float2*)(d_u + b * HDIM);
        float2 u0 = ubp[lane];
        float2 u1 = ubp[lane + 32];
        float cb = d_c[b];
#pragma unroll
        for (int r = 0; r < 8; r++) {
            float m0, m1, m2, m3;
            unpack2(acc0[r], m0, m1);
            unpack2(acc1[r], m2, m3);
            float sum = fmaxf(m0 + bmp0.x, 0.f) * u0.x
                      + fmaxf(m1 + bmp0.y, 0.f) * u0.y
                      + fmaxf(m2 + bmp1.x, 0.f) * u1.x
                      + fmaxf(m3 + bmp1.y, 0.f) * u1.y;
#pragma unroll
            for (int o = 16; o > 0; o >>= 1)
                sum += __shfl_down_sync(0xffffffffu, sum, o);
            if (lane == 0) q[tile * 8 + r] = sum + cb;
        }
        __syncwarp();
    }
}

// ---------------- launch ---------------------------------------------------------
extern "C" void kernel_launch(void* const* d_in, const int* in_sizes, int n_in,
                              void* d_out, int out_size) {
    const float* x       = (const float*)d_in[0];
    const int*   ei      = (const int*)  d_in[1];
    const int*   ne      = (const int*)  d_in[2];
    const int*   targets = (const int*)  d_in[3];
    const int*   regions = (const int*)  d_in[4];
    const float* W1l     = (const float*)d_in[5];
    const float* W1r     = (const float*)d_in[6];
    const float* b1      = (const float*)d_in[7];
    const float* W2l     = (const float*)d_in[8];
    const float* W2r     = (const float*)d_in[9];
    const float* b2      = (const float*)d_in[10];
    const float* Wm      = (const float*)d_in[11];
    const float* bm      = (const float*)d_in[12];
    const float* Wo      = (const float*)d_in[13];
    const float* bo      = (const float*)d_in[14];
    float* q = (float*)d_out;

    float *p_yl, *p_yr, *p_gl, *p_gr;
    cudaGetSymbolAddress((void**)&p_yl, d_yl);
    cudaGetSymbolAddress((void**)&p_yr, d_yr);
    cudaGetSymbolAddress((void**)&p_gl, d_gl);
    cudaGetSymbolAddress((void**)&p_gr, d_gr);

    // 1. clear scratch
    clear_kernel<<<(CLR_TOTAL + 255) / 256, 256>>>();

    // 2. slot assignment (independent of GEMMs, needs clear)
    slot_kernel<<<(BGRAPH * (AREG + 1) + 255) / 256, 256>>>(targets, regions);

    // 3. yl = x@W1l ; yr = x@W1r + b1
    dual_gemm_kernel<FIN, false><<<(NNODES + 63) / 64, 256>>>(
        x, W1l, W1r, b1, p_yl, p_yr, NNODES);

    // 4. conv1 scatter (8 edges/warp)
    {
        int warps = E1N / 8;                       // 100000
        int blocks = (warps * 32 + 255) / 256;
        scatter1_kernel<<<blocks, 256>>>(ei);
    }

    // 5. gl = h1@W2l ; gr = h1@W2r + b2 (h1 computed in the loader)
    dual_gemm_kernel<DDIM, true><<<(NNODES + 63) / 64, 256>>>(
        nullptr, W2l, W2r, b2, p_gl, p_gr, NNODES);

    // 6. conv2 scatter, needed dsts only
    scatter2_kernel<<<(BGRAPH * E2N) / 256, 256>>>(ne);

    // 7. h2 at needed slots
    {
        int warps = BGRAPH * (AREG + 1);
        h2_kernel<<<(warps * 32 + 255) / 256, 256>>>(targets, regions);
    }

    // 8. u_b = Wo @ t_b, c_b
    u_kernel<<<(BGRAPH * HDIM + 255) / 256, 256>>>(targets, Wo, bo);

    // 9. readout
    final_kernel<<<250, 256>>>(regions, Wm, bm, q);
}

// round 5
// speedup vs baseline: 1.2510x; 1.0149x over previous
#include <cuda_runtime.h>

#define NNODES 50000
#define FIN    128
#define DDIM   64
#define HDIM   128
#define BGRAPH 16
#define E1N    800000
#define E2N    200000
#define AREG   2000
#define SLOTS  2048

typedef unsigned long long ull;

// ---------------- f32x2 helpers --------------------------------------------------
__device__ __forceinline__ ull ffma2(ull a, ull b, ull c) {
    ull d;
    asm("fma.rn.f32x2 %0, %1, %2, %3;" : "=l"(d) : "l"(a), "l"(b), "l"(c));
    return d;
}
__device__ __forceinline__ ull pack2(float lo, float hi) {
    ull r;
    asm("mov.b64 %0, {%1, %2};" : "=l"(r) : "f"(lo), "f"(hi));
    return r;
}
__device__ __forceinline__ void unpack2(ull v, float& lo, float& hi) {
    asm("mov.b64 {%0, %1}, %2;" : "=f"(lo), "=f"(hi) : "l"(v));
}

// ---------------- scratch (device globals; no allocation allowed) ----------------
__device__ __align__(16) float d_yl[NNODES * DDIM];     // x @ W1l
__device__ __align__(16) float d_yr[NNODES * DDIM];     // x @ W1r + b1
__device__ __align__(16) float d_agg1[NNODES * DDIM];   // conv1 neighbor sum of yl
__device__ __align__(16) float d_deg1[NNODES];
__device__ __align__(16) float d_gl[NNODES * DDIM];     // h1 @ W2l
__device__ __align__(16) float d_gr[NNODES * DDIM];     // h1 @ W2r + b2
__device__ __align__(16) int   d_slotmap[BGRAPH * NNODES];
__device__ __align__(16) int   d_counter[BGRAPH];
__device__ __align__(16) float d_acc2[BGRAPH * SLOTS * DDIM];
__device__ __align__(16) float d_deg2[BGRAPH * SLOTS];
__device__ __align__(16) float d_u[BGRAPH * HDIM];      // Wo @ target_embed
__device__ __align__(16) float d_c[BGRAPH];             // bo . target_embed

// ---------------- clear kernel ---------------------------------------------------
static constexpr int CLR_AGG1 = NNODES * DDIM / 4;
static constexpr int CLR_ACC2 = BGRAPH * SLOTS * DDIM / 4;
static constexpr int CLR_SMAP = BGRAPH * NNODES / 4;
static constexpr int CLR_DEG1 = NNODES / 4;
static constexpr int CLR_DEG2 = BGRAPH * SLOTS / 4;
static constexpr int CLR_CNT  = BGRAPH / 4;
static constexpr int CLR_TOTAL = CLR_AGG1 + CLR_ACC2 + CLR_SMAP + CLR_DEG1 + CLR_DEG2 + CLR_CNT;

__global__ void clear_kernel() {
    int i = blockIdx.x * blockDim.x + threadIdx.x;
    float4 z = make_float4(0.f, 0.f, 0.f, 0.f);
    if (i < CLR_AGG1) { ((float4*)d_agg1)[i] = z; return; }
    i -= CLR_AGG1;
    if (i < CLR_ACC2) { ((float4*)d_acc2)[i] = z; return; }
    i -= CLR_ACC2;
    if (i < CLR_SMAP) { ((int4*)d_slotmap)[i] = make_int4(-1, -1, -1, -1); return; }
    i -= CLR_SMAP;
    if (i < CLR_DEG1) { ((float4*)d_deg1)[i] = z; return; }
    i -= CLR_DEG1;
    if (i < CLR_DEG2) { ((float4*)d_deg2)[i] = z; return; }
    i -= CLR_DEG2;
    if (i < CLR_CNT)  { ((int4*)d_counter)[i] = make_int4(0, 0, 0, 0); }
}

// ---------------- dual GEMM (f32x2 packed, LDS.128 A loads) ---------------------
// A [nrows, K] row-major, W [K, 64]. FUSE_H1: A row computed on the fly as
// relu(agg1/deg1 + yr).
template <int K, bool FUSE_H1>
__global__ void dual_gemm_kernel(const float* __restrict__ A,
                                 const float* __restrict__ W1,
                                 const float* __restrict__ W2,
                                 const float* __restrict__ bias,
                                 float* __restrict__ C1,
                                 float* __restrict__ C2,
                                 int nrows) {
    __shared__ float sA[32][68];      // 272B row stride: 16B-aligned rows
    __shared__ float sW1[32][128];    // duplicated pairs: [kk][2c]=[kk][2c+1]=w
    __shared__ float sW2[32][128];

    const int t = threadIdx.x;
    const int tx = t & 63;          // output column
    const int ty = t >> 6;          // 0..3 -> rows ty*16 .. ty*16+15
    const int row0 = blockIdx.x * 64;

    ull acc1[8], acc2[8];
#pragma unroll
    for (int i = 0; i < 8; i++) { acc1[i] = 0ull; acc2[i] = 0ull; }

    for (int k0 = 0; k0 < K; k0 += 32) {
#pragma unroll
        for (int i = 0; i < 8; i++) {
            int idx = t + i * 256;       // 0..2047
            int r = idx >> 5, kk = idx & 31;
            int row = row0 + r;
            float v = 0.f;
            if (row < nrows) {
                if (FUSE_H1) {
                    float inv = 1.f / fmaxf(d_deg1[row], 1.f);
                    v = fmaxf(d_agg1[row * 64 + k0 + kk] * inv +
                              d_yr[row * 64 + k0 + kk], 0.f);
                } else {
                    v = A[row * K + k0 + kk];
                }
            }
            sA[kk][r] = v;
        }
#pragma unroll
        for (int i = 0; i < 8; i++) {
            int idx = t + i * 256;
            int kk = idx >> 6, c = idx & 63;
            float w1 = W1[(k0 + kk) * 64 + c];
            float w2 = W2[(k0 + kk) * 64 + c];
            sW1[kk][2 * c] = w1; sW1[kk][2 * c + 1] = w1;
            sW2[kk][2 * c] = w2; sW2[kk][2 * c + 1] = w2;
        }
        __syncthreads();
#pragma unroll
        for (int kk = 0; kk < 32; kk++) {
            ull w1 = ((const ull*)&sW1[kk][0])[tx];
            ull w2 = ((const ull*)&sW2[kk][0])[tx];
            const ulonglong2* ap2 = (const ulonglong2*)&sA[kk][ty * 16];
#pragma unroll
            for (int u2 = 0; u2 < 4; u2++) {
                ulonglong2 av = ap2[u2];
                acc1[2 * u2]     = ffma2(av.x, w1, acc1[2 * u2]);
                acc2[2 * u2]     = ffma2(av.x, w2, acc2[2 * u2]);
                acc1[2 * u2 + 1] = ffma2(av.y, w1, acc1[2 * u2 + 1]);
                acc2[2 * u2 + 1] = ffma2(av.y, w2, acc2[2 * u2 + 1]);
            }
        }
        __syncthreads();
    }
    float bb = bias[tx];
#pragma unroll
    for (int u = 0; u < 8; u++) {
        float l1, h1v, l2, h2v;
        unpack2(acc1[u], l1, h1v);
        unpack2(acc2[u], l2, h2v);
        int row = row0 + ty * 16 + 2 * u;
        if (row < nrows) {
            C1[row * 64 + tx] = l1;
            C2[row * 64 + tx] = l2 + bb;
        }
        if (row + 1 < nrows) {
            C1[(row + 1) * 64 + tx] = h1v;
            C2[(row + 1) * 64 + tx] = h2v + bb;
        }
    }
}

// ---------------- conv1 edge scatter: agg1[dst] += yl[src], deg1[dst]++ ---------
// 16 edges per warp: half-warp handles 8 edges, deep-batched for MLP.
// E1N % 16 == 0 so no bounds checks.
__global__ void scatter1_kernel(const int* __restrict__ ei) {
    int tid = blockIdx.x * blockDim.x + threadIdx.x;
    int w = tid >> 5, lane = tid & 31;
    int e0 = 16 * w + (lane >> 4);      // this half-warp: e0, e0+2, ..., e0+14
    int j = lane & 15;

    int src[8], dst[8];
#pragma unroll
    for (int i = 0; i < 8; i++) {
        src[i] = ei[e0 + 2 * i];
        dst[i] = ei[E1N + e0 + 2 * i];
    }
    float4 v[8];
#pragma unroll
    for (int i = 0; i < 8; i++)
        v[i] = ((const float4*)(d_yl + src[i] * 64))[j];
#pragma unroll
    for (int i = 0; i < 8; i++) {
        float* p = d_agg1 + dst[i] * 64 + 4 * j;
        asm volatile("red.global.add.v4.f32 [%0], {%1,%2,%3,%4};"
                     :: "l"(p), "f"(v[i].x), "f"(v[i].y), "f"(v[i].z), "f"(v[i].w)
                     : "memory");
    }
    if (j == 0) {
#pragma unroll
        for (int i = 0; i < 8; i++)
            atomicAdd(&d_deg1[dst[i]], 1.0f);
    }
}

// ---------------- per-graph needed-node slot assignment -------------------------
__global__ void slot_kernel(const int* __restrict__ targets,
                            const int* __restrict__ regions) {
    int idx = blockIdx.x * blockDim.x + threadIdx.x;
    if (idx >= BGRAPH * (AREG + 1)) return;
    int b = idx / (AREG + 1);
    int j = idx % (AREG + 1);
    int node = (j == AREG) ? targets[b] : regions[b * AREG + j];
    int* p = &d_slotmap[b * NNODES + node];
    if (atomicCAS(p, -1, -2) == -1) {
        int s = atomicAdd(&d_counter[b], 1);
        atomicExch(p, s);
    }
}

// ---------------- conv2 edge scatter (only needed destinations) -----------------
__global__ void scatter2_kernel(const int* __restrict__ ne) {
    int idx = blockIdx.x * blockDim.x + threadIdx.x;
    int lane = threadIdx.x & 31;
    int b = idx / E2N;                  // uniform per warp (E2N % 32 == 0)
    int e = idx - b * E2N;
    int slot = -1, src = 0;
    int dst = ne[b * 2 * E2N + E2N + e];
    slot = d_slotmap[b * NNODES + dst];
    if (slot >= 0) src = ne[b * 2 * E2N + e];
    unsigned mask = __ballot_sync(0xffffffffu, slot >= 0);
    while (mask) {
        int bit = __ffs(mask) - 1;
        mask &= mask - 1;
        int es = __shfl_sync(0xffffffffu, src, bit);
        int sl = __shfl_sync(0xffffffffu, slot, bit);
        float2 v = ((const float2*)(d_gl + es * 64))[lane];
        float* p = d_acc2 + (b * SLOTS + sl) * 64 + 2 * lane;
        asm volatile("red.global.add.v2.f32 [%0], {%1,%2};"
                     :: "l"(p), "f"(v.x), "f"(v.y) : "memory");
        if (lane == 0) atomicAdd(&d_deg2[b * SLOTS + sl], 1.0f);
    }
}

// ---------------- u_b = Wo @ t_b , c_b = bo . t_b (t computed on the fly) -------
__global__ void u_kernel(const int* __restrict__ targets,
                         const float* __restrict__ Wo,
                         const float* __restrict__ bo) {
    int idx = blockIdx.x * blockDim.x + threadIdx.x;
    if (idx >= BGRAPH * HDIM) return;
    int b = idx >> 7;
    int h = idx & 127;
    int node = targets[b];
    int s = d_slotmap[b * NNODES + node];
    int base = (b * SLOTS + s) * 64;
    float inv = 1.f / fmaxf(d_deg2[b * SLOTS + s], 1.f);
    float acc = 0.f, c = 0.f;
#pragma unroll
    for (int d = 0; d < 64; d++) {
        float td = fmaxf(d_acc2[base + d] * inv + d_gr[node * 64 + d], 0.f);
        acc += Wo[h * 64 + d] * td;
        c += bo[d] * td;
    }
    d_u[idx] = acc;
    if (h == 0) d_c[b] = c;
}

// ---------------- final readout: q[p] = relu(h2_reg@Wm+bm).u_b + c_b ------------
// region h2 computed on the fly from acc2/deg2/gr (h2 kernel removed).
__global__ void final_kernel(const int* __restrict__ regions,
                             const float* __restrict__ Wm,
                             const float* __restrict__ bm,
                             float* __restrict__ q) {
    __shared__ float sWm[64 * 128];   // 32 KB
    __shared__ float sreg[8][8][64];  // 16 KB
    for (int i = threadIdx.x; i < 64 * 128; i += blockDim.x)
        sWm[i] = Wm[i];
    __syncthreads();

    const int lane = threadIdx.x & 31;
    const int wl = threadIdx.x >> 5;
    const float2 bmp0 = ((const float2*)bm)[lane];
    const float2 bmp1 = ((const float2*)bm)[lane + 32];

    for (int tile = blockIdx.x * 8 + wl; tile < 4000; tile += gridDim.x * 8) {
        int b = tile / 250;
#pragma unroll
        for (int r = 0; r < 8; r++) {
            int p = tile * 8 + r;
            int node = regions[p];
            int s = d_slotmap[b * NNODES + node];
            int base = (b * SLOTS + s) * 64;
            float inv = 1.f / fmaxf(d_deg2[b * SLOTS + s], 1.f);
            float2 a = ((const float2*)(d_acc2 + base))[lane];
            float2 g = ((const float2*)(d_gr + node * 64))[lane];
            sreg[wl][r][2 * lane]     = fmaxf(a.x * inv + g.x, 0.f);
            sreg[wl][r][2 * lane + 1] = fmaxf(a.y * inv + g.y, 0.f);
        }
        __syncwarp();

        ull acc0[8], acc1[8];
#pragma unroll
        for (int r = 0; r < 8; r++) { acc0[r] = 0ull; acc1[r] = 0ull; }

#pragma unroll 8
        for (int d = 0; d < 64; d++) {
            ull w0 = ((const ull*)(sWm + d * 128))[lane];
            ull w1 = ((const ull*)(sWm + d * 128 + 64))[lane];
#pragma unroll
            for (int r = 0; r < 8; r++) {
                float rd = sreg[wl][r][d];
                ull rdp = pack2(rd, rd);
                acc0[r] = ffma2(rdp, w0, acc0[r]);
                acc1[r] = ffma2(rdp, w1, acc1[r]);
            }
        }

        const float2* ubp = (const float2*)(d_u + b * HDIM);
        float2 u0 = ubp[lane];
        float2 u1 = ubp[lane + 32];
        float cb = d_c[b];
#pragma unroll
        for (int r = 0; r < 8; r++) {
            float m0, m1, m2, m3;
            unpack2(acc0[r], m0, m1);
            unpack2(acc1[r], m2, m3);
            float sum = fmaxf(m0 + bmp0.x, 0.f) * u0.x
                      + fmaxf(m1 + bmp0.y, 0.f) * u0.y
                      + fmaxf(m2 + bmp1.x, 0.f) * u1.x
                      + fmaxf(m3 + bmp1.y, 0.f) * u1.y;
#pragma unroll
            for (int o = 16; o > 0; o >>= 1)
                sum += __shfl_down_sync(0xffffffffu, sum, o);
            if (lane == 0) q[tile * 8 + r] = sum + cb;
        }
        __syncwarp();
    }
}

// ---------------- launch ---------------------------------------------------------
extern "C" void kernel_launch(void* const* d_in, const int* in_sizes, int n_in,
                              void* d_out, int out_size) {
    const float* x       = (const float*)d_in[0];
    const int*   ei      = (const int*)  d_in[1];
    const int*   ne      = (const int*)  d_in[2];
    const int*   targets = (const int*)  d_in[3];
    const int*   regions = (const int*)  d_in[4];
    const float* W1l     = (const float*)d_in[5];
    const float* W1r     = (const float*)d_in[6];
    const float* b1      = (const float*)d_in[7];
    const float* W2l     = (const float*)d_in[8];
    const float* W2r     = (const float*)d_in[9];
    const float* b2      = (const float*)d_in[10];
    const float* Wm      = (const float*)d_in[11];
    const float* bm      = (const float*)d_in[12];
    const float* Wo      = (const float*)d_in[13];
    const float* bo      = (const float*)d_in[14];
    float* q = (float*)d_out;

    float *p_yl, *p_yr, *p_gl, *p_gr;
    cudaGetSymbolAddress((void**)&p_yl, d_yl);
    cudaGetSymbolAddress((void**)&p_yr, d_yr);
    cudaGetSymbolAddress((void**)&p_gl, d_gl);
    cudaGetSymbolAddress((void**)&p_gr, d_gr);

    // 1. clear scratch
    clear_kernel<<<(CLR_TOTAL + 255) / 256, 256>>>();

    // 2. slot assignment
    slot_kernel<<<(BGRAPH * (AREG + 1) + 255) / 256, 256>>>(targets, regions);

    // 3. yl = x@W1l ; yr = x@W1r + b1
    dual_gemm_kernel<FIN, false><<<(NNODES + 63) / 64, 256>>>(
        x, W1l, W1r, b1, p_yl, p_yr, NNODES);

    // 4. conv1 scatter (16 edges/warp)
    {
        int warps = E1N / 16;                      // 50000
        int blocks = (warps * 32 + 255) / 256;
        scatter1_kernel<<<blocks, 256>>>(ei);
    }

    // 5. gl = h1@W2l ; gr = h1@W2r + b2 (h1 computed in the loader)
    dual_gemm_kernel<DDIM, true><<<(NNODES + 63) / 64, 256>>>(
        nullptr, W2l, W2r, b2, p_gl, p_gr, NNODES);

    // 6. conv2 scatter, needed dsts only
    scatter2_kernel<<<(BGRAPH * E2N) / 256, 256>>>(ne);

    // 7. u_b = Wo @ t_b, c_b (target h2 on the fly)
    u_kernel<<<(BGRAPH * HDIM + 255) / 256, 256>>>(targets, Wo, bo);

    // 8. readout (region h2 on the fly)
    final_kernel<<<250, 256>>>(regions, Wm, bm, q);
}

// round 6
// speedup vs baseline: 1.2548x; 1.0030x over previous
#include <cuda_runtime.h>

#define NNODES 50000
#define FIN    128
#define DDIM   64
#define HDIM   128
#define BGRAPH 16
#define E1N    800000
#define E2N    200000
#define AREG   2000
#define SLOTS  2048
#define BMWORDS 1568   // ceil(50000/32)=1563, padded to multiple of 4

typedef unsigned long long ull;

// ---------------- f32x2 helpers --------------------------------------------------
__device__ __forceinline__ ull ffma2(ull a, ull b, ull c) {
    ull d;
    asm("fma.rn.f32x2 %0, %1, %2, %3;" : "=l"(d) : "l"(a), "l"(b), "l"(c));
    return d;
}
__device__ __forceinline__ ull pack2(float lo, float hi) {
    ull r;
    asm("mov.b64 %0, {%1, %2};" : "=l"(r) : "f"(lo), "f"(hi));
    return r;
}
__device__ __forceinline__ void unpack2(ull v, float& lo, float& hi) {
    asm("mov.b64 {%0, %1}, %2;" : "=f"(lo), "=f"(hi) : "l"(v));
}

// ---------------- scratch (device globals; no allocation allowed) ----------------
__device__ __align__(16) float d_yl[NNODES * DDIM];
__device__ __align__(16) float d_yr[NNODES * DDIM];
__device__ __align__(16) float d_agg1[NNODES * DDIM];
__device__ __align__(16) float d_deg1[NNODES];
__device__ __align__(16) float d_gl[NNODES * DDIM];
__device__ __align__(16) float d_gr[NNODES * DDIM];
__device__ __align__(16) int   d_slotmap[BGRAPH * NNODES];
__device__ __align__(16) unsigned d_bitmap[BGRAPH * BMWORDS];
__device__ __align__(16) int   d_counter[BGRAPH];
__device__ __align__(16) float d_acc2[BGRAPH * SLOTS * DDIM];
__device__ __align__(16) float d_deg2[BGRAPH * SLOTS];
__device__ __align__(16) float d_u[BGRAPH * HDIM];
__device__ __align__(16) float d_c[BGRAPH];

// ---------------- clear kernel ---------------------------------------------------
static constexpr int CLR_AGG1 = NNODES * DDIM / 4;
static constexpr int CLR_ACC2 = BGRAPH * SLOTS * DDIM / 4;
static constexpr int CLR_SMAP = BGRAPH * NNODES / 4;
static constexpr int CLR_BMAP = BGRAPH * BMWORDS / 4;
static constexpr int CLR_DEG1 = NNODES / 4;
static constexpr int CLR_DEG2 = BGRAPH * SLOTS / 4;
static constexpr int CLR_CNT  = BGRAPH / 4;
static constexpr int CLR_TOTAL = CLR_AGG1 + CLR_ACC2 + CLR_SMAP + CLR_BMAP +
                                 CLR_DEG1 + CLR_DEG2 + CLR_CNT;

__global__ void clear_kernel() {
    int i = blockIdx.x * blockDim.x + threadIdx.x;
    float4 z = make_float4(0.f, 0.f, 0.f, 0.f);
    if (i < CLR_AGG1) { ((float4*)d_agg1)[i] = z; return; }
    i -= CLR_AGG1;
    if (i < CLR_ACC2) { ((float4*)d_acc2)[i] = z; return; }
    i -= CLR_ACC2;
    if (i < CLR_SMAP) { ((int4*)d_slotmap)[i] = make_int4(-1, -1, -1, -1); return; }
    i -= CLR_SMAP;
    if (i < CLR_BMAP) { ((uint4*)d_bitmap)[i] = make_uint4(0, 0, 0, 0); return; }
    i -= CLR_BMAP;
    if (i < CLR_DEG1) { ((float4*)d_deg1)[i] = z; return; }
    i -= CLR_DEG1;
    if (i < CLR_DEG2) { ((float4*)d_deg2)[i] = z; return; }
    i -= CLR_DEG2;
    if (i < CLR_CNT)  { ((int4*)d_counter)[i] = make_int4(0, 0, 0, 0); }
}

// ---------------- dual GEMM (f32x2 packed, LDS.128 A loads) ---------------------
template <int K, bool FUSE_H1>
__global__ void dual_gemm_kernel(const float* __restrict__ A,
                                 const float* __restrict__ W1,
                                 const float* __restrict__ W2,
                                 const float* __restrict__ bias,
                                 float* __restrict__ C1,
                                 float* __restrict__ C2,
                                 int nrows) {
    __shared__ float sA[32][68];
    __shared__ float sW1[32][128];
    __shared__ float sW2[32][128];

    const int t = threadIdx.x;
    const int tx = t & 63;
    const int ty = t >> 6;
    const int row0 = blockIdx.x * 64;

    ull acc1[8], acc2[8];
#pragma unroll
    for (int i = 0; i < 8; i++) { acc1[i] = 0ull; acc2[i] = 0ull; }

    for (int k0 = 0; k0 < K; k0 += 32) {
#pragma unroll
        for (int i = 0; i < 8; i++) {
            int idx = t + i * 256;
            int r = idx >> 5, kk = idx & 31;
            int row = row0 + r;
            float v = 0.f;
            if (row < nrows) {
                if (FUSE_H1) {
                    float inv = 1.f / fmaxf(d_deg1[row], 1.f);
                    v = fmaxf(d_agg1[row * 64 + k0 + kk] * inv +
                              d_yr[row * 64 + k0 + kk], 0.f);
                } else {
                    v = A[row * K + k0 + kk];
                }
            }
            sA[kk][r] = v;
        }
#pragma unroll
        for (int i = 0; i < 8; i++) {
            int idx = t + i * 256;
            int kk = idx >> 6, c = idx & 63;
            float w1 = W1[(k0 + kk) * 64 + c];
            float w2 = W2[(k0 + kk) * 64 + c];
            sW1[kk][2 * c] = w1; sW1[kk][2 * c + 1] = w1;
            sW2[kk][2 * c] = w2; sW2[kk][2 * c + 1] = w2;
        }
        __syncthreads();
#pragma unroll
        for (int kk = 0; kk < 32; kk++) {
            ull w1 = ((const ull*)&sW1[kk][0])[tx];
            ull w2 = ((const ull*)&sW2[kk][0])[tx];
            const ulonglong2* ap2 = (const ulonglong2*)&sA[kk][ty * 16];
#pragma unroll
            for (int u2 = 0; u2 < 4; u2++) {
                ulonglong2 av = ap2[u2];
                acc1[2 * u2]     = ffma2(av.x, w1, acc1[2 * u2]);
                acc2[2 * u2]     = ffma2(av.x, w2, acc2[2 * u2]);
                acc1[2 * u2 + 1] = ffma2(av.y, w1, acc1[2 * u2 + 1]);
                acc2[2 * u2 + 1] = ffma2(av.y, w2, acc2[2 * u2 + 1]);
            }
        }
        __syncthreads();
    }
    float bb = bias[tx];
#pragma unroll
    for (int u = 0; u < 8; u++) {
        float l1, h1v, l2, h2v;
        unpack2(acc1[u], l1, h1v);
        unpack2(acc2[u], l2, h2v);
        int row = row0 + ty * 16 + 2 * u;
        if (row < nrows) {
            C1[row * 64 + tx] = l1;
            C2[row * 64 + tx] = l2 + bb;
        }
        if (row + 1 < nrows) {
            C1[(row + 1) * 64 + tx] = h1v;
            C2[(row + 1) * 64 + tx] = h2v + bb;
        }
    }
}

// ---------------- conv1 edge scatter (8 edges/warp) -----------------------------
__global__ void scatter1_kernel(const int* __restrict__ ei) {
    int tid = blockIdx.x * blockDim.x + threadIdx.x;
    int w = tid >> 5, lane = tid & 31;
    int e0 = 8 * w + (lane >> 4);
    int j = lane & 15;

    int s0 = ei[e0];
    int s1 = ei[e0 + 2];
    int s2 = ei[e0 + 4];
    int s3 = ei[e0 + 6];
    int dd0 = ei[E1N + e0];
    int dd1 = ei[E1N + e0 + 2];
    int dd2 = ei[E1N + e0 + 4];
    int dd3 = ei[E1N + e0 + 6];

    float4 v0 = ((const float4*)(d_yl + s0 * 64))[j];
    float4 v1 = ((const float4*)(d_yl + s1 * 64))[j];
    float4 v2 = ((const float4*)(d_yl + s2 * 64))[j];
    float4 v3 = ((const float4*)(d_yl + s3 * 64))[j];

    float* p0 = d_agg1 + dd0 * 64 + 4 * j;
    float* p1 = d_agg1 + dd1 * 64 + 4 * j;
    float* p2 = d_agg1 + dd2 * 64 + 4 * j;
    float* p3 = d_agg1 + dd3 * 64 + 4 * j;
    asm volatile("red.global.add.v4.f32 [%0], {%1,%2,%3,%4};"
                 :: "l"(p0), "f"(v0.x), "f"(v0.y), "f"(v0.z), "f"(v0.w) : "memory");
    asm volatile("red.global.add.v4.f32 [%0], {%1,%2,%3,%4};"
                 :: "l"(p1), "f"(v1.x), "f"(v1.y), "f"(v1.z), "f"(v1.w) : "memory");
    asm volatile("red.global.add.v4.f32 [%0], {%1,%2,%3,%4};"
                 :: "l"(p2), "f"(v2.x), "f"(v2.y), "f"(v2.z), "f"(v2.w) : "memory");
    asm volatile("red.global.add.v4.f32 [%0], {%1,%2,%3,%4};"
                 :: "l"(p3), "f"(v3.x), "f"(v3.y), "f"(v3.z), "f"(v3.w) : "memory");
    if (j == 0) {
        atomicAdd(&d_deg1[dd0], 1.0f);
        atomicAdd(&d_deg1[dd1], 1.0f);
        atomicAdd(&d_deg1[dd2], 1.0f);
        atomicAdd(&d_deg1[dd3], 1.0f);
    }
}

// ---------------- per-graph needed-node slot assignment + bitmap ----------------
__global__ void slot_kernel(const int* __restrict__ targets,
                            const int* __restrict__ regions) {
    int idx = blockIdx.x * blockDim.x + threadIdx.x;
    if (idx >= BGRAPH * (AREG + 1)) return;
    int b = idx / (AREG + 1);
    int j = idx % (AREG + 1);
    int node = (j == AREG) ? targets[b] : regions[b * AREG + j];
    atomicOr(&d_bitmap[b * BMWORDS + (node >> 5)], 1u << (node & 31));
    int* p = &d_slotmap[b * NNODES + node];
    if (atomicCAS(p, -1, -2) == -1) {
        int s = atomicAdd(&d_counter[b], 1);
        atomicExch(p, s);
    }
}

// ---------------- conv2 edge scatter with smem bitmap filter --------------------
// grid (125, 16), block 320: each block handles 1600 edges of graph blockIdx.y.
__global__ void scatter2_kernel(const int* __restrict__ ne) {
    __shared__ unsigned sbm[BMWORDS];
    const int b = blockIdx.y;
    for (int i = threadIdx.x; i < BMWORDS; i += 320)
        sbm[i] = d_bitmap[b * BMWORDS + i];
    __syncthreads();

    const int lane = threadIdx.x & 31;
    const long base = (long)b * 2 * E2N;
    int e0 = blockIdx.x * 1600 + threadIdx.x;
#pragma unroll
    for (int it = 0; it < 5; it++) {
        int e = e0 + it * 320;
        int dst = ne[base + E2N + e];
        bool hit = (sbm[dst >> 5] >> (dst & 31)) & 1u;
        int slot = -1, src = 0;
        if (hit) {
            slot = d_slotmap[b * NNODES + dst];
            src = ne[base + e];
        }
        unsigned mask = __ballot_sync(0xffffffffu, hit);
        while (mask) {
            int bit = __ffs(mask) - 1;
            mask &= mask - 1;
            int es = __shfl_sync(0xffffffffu, src, bit);
            int sl = __shfl_sync(0xffffffffu, slot, bit);
            float2 v = ((const float2*)(d_gl + es * 64))[lane];
            float* p = d_acc2 + (b * SLOTS + sl) * 64 + 2 * lane;
            asm volatile("red.global.add.v2.f32 [%0], {%1,%2};"
                         :: "l"(p), "f"(v.x), "f"(v.y) : "memory");
            if (lane == 0) atomicAdd(&d_deg2[b * SLOTS + sl], 1.0f);
        }
    }
}

// ---------------- u_b = Wo @ t_b , c_b = bo . t_b (t computed on the fly) -------
__global__ void u_kernel(const int* __restrict__ targets,
                         const float* __restrict__ Wo,
                         const float* __restrict__ bo) {
    int idx = blockIdx.x * blockDim.x + threadIdx.x;
    if (idx >= BGRAPH * HDIM) return;
    int b = idx >> 7;
    int h = idx & 127;
    int node = targets[b];
    int s = d_slotmap[b * NNODES + node];
    int base = (b * SLOTS + s) * 64;
    float inv = 1.f / fmaxf(d_deg2[b * SLOTS + s], 1.f);
    float acc = 0.f, c = 0.f;
#pragma unroll
    for (int d = 0; d < 64; d++) {
        float td = fmaxf(d_acc2[base + d] * inv + d_gr[node * 64 + d], 0.f);
        acc += Wo[h * 64 + d] * td;
        c += bo[d] * td;
    }
    d_u[idx] = acc;
    if (h == 0) d_c[b] = c;
}

// ---------------- final readout: q[p] = relu(h2_reg@Wm+bm).u_b + c_b ------------
__global__ void final_kernel(const int* __restrict__ regions,
                             const float* __restrict__ Wm,
                             const float* __restrict__ bm,
                             float* __restrict__ q) {
    __shared__ float sWm[64 * 128];
    __shared__ float sreg[8][8][64];
    for (int i = threadIdx.x; i < 64 * 128; i += blockDim.x)
        sWm[i] = Wm[i];
    __syncthreads();

    const int lane = threadIdx.x & 31;
    const int wl = threadIdx.x >> 5;
    const float2 bmp0 = ((const float2*)bm)[lane];
    const float2 bmp1 = ((const float2*)bm)[lane + 32];

    for (int tile = blockIdx.x * 8 + wl; tile < 4000; tile += gridDim.x * 8) {
        int b = tile / 250;
#pragma unroll
        for (int r = 0; r < 8; r++) {
            int p = tile * 8 + r;
            int node = regions[p];
            int s = d_slotmap[b * NNODES + node];
            int base = (b * SLOTS + s) * 64;
            float inv = 1.f / fmaxf(d_deg2[b * SLOTS + s], 1.f);
            float2 a = ((const float2*)(d_acc2 + base))[lane];
            float2 g = ((const float2*)(d_gr + node * 64))[lane];
            sreg[wl][r][2 * lane]     = fmaxf(a.x * inv + g.x, 0.f);
            sreg[wl][r][2 * lane + 1] = fmaxf(a.y * inv + g.y, 0.f);
        }
        __syncwarp();

        ull acc0[8], acc1[8];
#pragma unroll
        for (int r = 0; r < 8; r++) { acc0[r] = 0ull; acc1[r] = 0ull; }

#pragma unroll 8
        for (int d = 0; d < 64; d++) {
            ull w0 = ((const ull*)(sWm + d * 128))[lane];
            ull w1 = ((const ull*)(sWm + d * 128 + 64))[lane];
#pragma unroll
            for (int r = 0; r < 8; r++) {
                float rd = sreg[wl][r][d];
                ull rdp = pack2(rd, rd);
                acc0[r] = ffma2(rdp, w0, acc0[r]);
                acc1[r] = ffma2(rdp, w1, acc1[r]);
            }
        }

        const float2* ubp = (const float2*)(d_u + b * HDIM);
        float2 u0 = ubp[lane];
        float2 u1 = ubp[lane + 32];
        float cb = d_c[b];
#pragma unroll
        for (int r = 0; r < 8; r++) {
            float m0, m1, m2, m3;
            unpack2(acc0[r], m0, m1);
            unpack2(acc1[r], m2, m3);
            float sum = fmaxf(m0 + bmp0.x, 0.f) * u0.x
                      + fmaxf(m1 + bmp0.y, 0.f) * u0.y
                      + fmaxf(m2 + bmp1.x, 0.f) * u1.x
                      + fmaxf(m3 + bmp1.y, 0.f) * u1.y;
#pragma unroll
            for (int o = 16; o > 0; o >>= 1)
                sum += __shfl_down_sync(0xffffffffu, sum, o);
            if (lane == 0) q[tile * 8 + r] = sum + cb;
        }
        __syncwarp();
    }
}

// ---------------- launch ---------------------------------------------------------
extern "C" void kernel_launch(void* const* d_in, const int* in_sizes, int n_in,
                              void* d_out, int out_size) {
    const float* x       = (const float*)d_in[0];
    const int*   ei      = (const int*)  d_in[1];
    const int*   ne      = (const int*)  d_in[2];
    const int*   targets = (const int*)  d_in[3];
    const int*   regions = (const int*)  d_in[4];
    const float* W1l     = (const float*)d_in[5];
    const float* W1r     = (const float*)d_in[6];
    const float* b1      = (const float*)d_in[7];
    const float* W2l     = (const float*)d_in[8];
    const float* W2r     = (const float*)d_in[9];
    const float* b2      = (const float*)d_in[10];
    const float* Wm      = (const float*)d_in[11];
    const float* bm      = (const float*)d_in[12];
    const float* Wo      = (const float*)d_in[13];
    const float* bo      = (const float*)d_in[14];
    float* q = (float*)d_out;

    float *p_yl, *p_yr, *p_gl, *p_gr;
    cudaGetSymbolAddress((void**)&p_yl, d_yl);
    cudaGetSymbolAddress((void**)&p_yr, d_yr);
    cudaGetSymbolAddress((void**)&p_gl, d_gl);
    cudaGetSymbolAddress((void**)&p_gr, d_gr);

    // 0. yl = x@W1l ; yr = x@W1r + b1  (needs only inputs)
    dual_gemm_kernel<FIN, false><<<(NNODES + 63) / 64, 256>>>(
        x, W1l, W1r, b1, p_yl, p_yr, NNODES);

    // 1. clear scratch
    clear_kernel<<<(CLR_TOTAL + 255) / 256, 256>>>();

    // 2. conv1 scatter (8 edges/warp)
    {
        int warps = E1N / 8;
        int blocks = (warps * 32 + 255) / 256;
        scatter1_kernel<<<blocks, 256>>>(ei);
    }

    // 3. gl = h1@W2l ; gr = h1@W2r + b2 (h1 fused)  <-- profiled slot
    dual_gemm_kernel<DDIM, true><<<(NNODES + 63) / 64, 256>>>(
        nullptr, W2l, W2r, b2, p_gl, p_gr, NNODES);

    // 4. slot assignment + bitmap
    slot_kernel<<<(BGRAPH * (AREG + 1) + 255) / 256, 256>>>(targets, regions);

    // 5. conv2 scatter with smem bitmap filter
    {
        dim3 grid(125, BGRAPH);
        scatter2_kernel<<<grid, 320>>>(ne);
    }

    // 6. u_b = Wo @ t_b, c_b
    u_kernel<<<(BGRAPH * HDIM + 255) / 256, 256>>>(targets, Wo, bo);

    // 7. readout
    final_kernel<<<250, 256>>>(regions, Wm, bm, q);
}

// round 8
// speedup vs baseline: 1.4349x; 1.1436x over previous
#include <cuda_runtime.h>
#include <cuda_bf16.h>

#define NNODES 50000
#define FIN    128
#define DDIM   64
#define HDIM   128
#define BGRAPH 16
#define E1N    800000
#define E2N    200000
#define AREG   2000
#define SLOTS  2048
#define BMWORDS 1568

typedef unsigned long long ull;
typedef unsigned int u32;

// ---------------- f32x2 / bf16 helpers ------------------------------------------
__device__ __forceinline__ ull ffma2(ull a, ull b, ull c) {
    ull d;
    asm("fma.rn.f32x2 %0, %1, %2, %3;" : "=l"(d) : "l"(a), "l"(b), "l"(c));
    return d;
}
__device__ __forceinline__ ull pack2(float lo, float hi) {
    ull r;
    asm("mov.b64 %0, {%1, %2};" : "=l"(r) : "f"(lo), "f"(hi));
    return r;
}
__device__ __forceinline__ void unpack2(ull v, float& lo, float& hi) {
    asm("mov.b64 {%0, %1}, %2;" : "=f"(lo), "=f"(hi) : "l"(v));
}
__device__ __forceinline__ u32 bf2_hi(float a, float b) {
    __nv_bfloat162 h = __floats2bfloat162_rn(a, b);
    return *reinterpret_cast<u32*>(&h);
}
__device__ __forceinline__ u32 bf2_lo(float a, float b) {
    float ra = a - __bfloat162float(__float2bfloat16(a));
    float rb = b - __bfloat162float(__float2bfloat16(b));
    __nv_bfloat162 l = __floats2bfloat162_rn(ra, rb);
    return *reinterpret_cast<u32*>(&l);
}
__device__ __forceinline__ void mma16816(float* c, u32 a0, u32 a1, u32 a2, u32 a3,
                                         u32 b0, u32 b1) {
    asm("mma.sync.aligned.m16n8k16.row.col.f32.bf16.bf16.f32 "
        "{%0,%1,%2,%3}, {%4,%5,%6,%7}, {%8,%9}, {%0,%1,%2,%3};"
        : "+f"(c[0]), "+f"(c[1]), "+f"(c[2]), "+f"(c[3])
        : "r"(a0), "r"(a1), "r"(a2), "r"(a3), "r"(b0), "r"(b1));
}

// ---------------- scratch -------------------------------------------------------
__device__ __align__(16) float d_yl[NNODES * DDIM];
__device__ __align__(16) float d_yr[NNODES * DDIM];
__device__ __align__(16) float d_agg1[NNODES * DDIM];
__device__ __align__(16) float d_deg1[NNODES];
__device__ __align__(16) float d_gl[NNODES * DDIM];
__device__ __align__(16) float d_gr[NNODES * DDIM];
__device__ __align__(16) int   d_slotmap[BGRAPH * NNODES];
__device__ __align__(16) unsigned d_bitmap[BGRAPH * BMWORDS];
__device__ __align__(16) int   d_counter[BGRAPH];
__device__ __align__(16) float d_acc2[BGRAPH * SLOTS * DDIM];
__device__ __align__(16) float d_deg2[BGRAPH * SLOTS];
__device__ __align__(16) float d_u[BGRAPH * HDIM];
__device__ __align__(16) float d_c[BGRAPH];

// ---------------- clear kernel --------------------------------------------------
static constexpr int CLR_AGG1 = NNODES * DDIM / 4;
static constexpr int CLR_ACC2 = BGRAPH * SLOTS * DDIM / 4;
static constexpr int CLR_SMAP = BGRAPH * NNODES / 4;
static constexpr int CLR_BMAP = BGRAPH * BMWORDS / 4;
static constexpr int CLR_DEG1 = NNODES / 4;
static constexpr int CLR_DEG2 = BGRAPH * SLOTS / 4;
static constexpr int CLR_CNT  = BGRAPH / 4;
static constexpr int CLR_TOTAL = CLR_AGG1 + CLR_ACC2 + CLR_SMAP + CLR_BMAP +
                                 CLR_DEG1 + CLR_DEG2 + CLR_CNT;

__global__ void clear_kernel() {
    int i = blockIdx.x * blockDim.x + threadIdx.x;
    float4 z = make_float4(0.f, 0.f, 0.f, 0.f);
    if (i < CLR_AGG1) { ((float4*)d_agg1)[i] = z; return; }
    i -= CLR_AGG1;
    if (i < CLR_ACC2) { ((float4*)d_acc2)[i] = z; return; }
    i -= CLR_ACC2;
    if (i < CLR_SMAP) { ((int4*)d_slotmap)[i] = make_int4(-1, -1, -1, -1); return; }
    i -= CLR_SMAP;
    if (i < CLR_BMAP) { ((uint4*)d_bitmap)[i] = make_uint4(0, 0, 0, 0); return; }
    i -= CLR_BMAP;
    if (i < CLR_DEG1) { ((float4*)d_deg1)[i] = z; return; }
    i -= CLR_DEG1;
    if (i < CLR_DEG2) { ((float4*)d_deg2)[i] = z; return; }
    i -= CLR_DEG2;
    if (i < CLR_CNT)  { ((int4*)d_counter)[i] = make_int4(0, 0, 0, 0); }
}

// ================= HMMA bf16-split dual GEMM ====================================
// Per CTA: D[128, 128] = A[128, K] @ [W1 | W2]; cols 0..63 -> C1, 64..127 -> C2+bias.
// bf16 split: D = Ah·Bh + Al·Bh + Ah·Bl (ll dropped, ~1.5e-5 rel).
// K staged in 32-wide chunks. Pair-permuted smem so each mma fragment = 1 LDS.64:
//   pair index jg (= k>>1, 0..15 per 16-k group): pp = ((jg>>2)&1) + (jg&3)*2 + (jg>>3)*8
//   row stride 48 bf16 (96B) -> 64-bit loads conflict-free (12g + t distinct mod 16).
template <int K, bool FUSE_H1>
__global__ __launch_bounds__(256) void mma_dual_gemm(const float* __restrict__ A,
                                                     const float* __restrict__ W1,
                                                     const float* __restrict__ W2,
                                                     const float* __restrict__ bias,
                                                     float* __restrict__ C1,
                                                     float* __restrict__ C2,
                                                     int nrows) {
    __shared__ __align__(16) __nv_bfloat16 sAh[128 * 48];
    __shared__ __align__(16) __nv_bfloat16 sAl[128 * 48];
    __shared__ __align__(16) __nv_bfloat16 sBh[128 * 48];
    __shared__ __align__(16) __nv_bfloat16 sBl[128 * 48];

    const int t = threadIdx.x;
    const int w = t >> 5, lane = t & 31;
    const int g = lane >> 2, tg = lane & 3;
    const int row0 = blockIdx.x * 128;

    float acc[16][4];
#pragma unroll
    for (int nt = 0; nt < 16; nt++)
#pragma unroll
        for (int i = 0; i < 4; i++) acc[nt][i] = 0.f;

    for (int k0 = 0; k0 < K; k0 += 32) {
        // ---- fill A chunk (rows row0..row0+127, k k0..k0+31), hi+lo ----
        {
            int r = t >> 1, half = t & 1;
            int row = row0 + r;
            float inv = 1.f;
            if (FUSE_H1 && row < nrows) inv = 1.f / fmaxf(d_deg1[row], 1.f);
#pragma unroll
            for (int j = 0; j < 8; j++) {
                int jg = half * 8 + j;
                int k = 2 * jg;
                float2 v = make_float2(0.f, 0.f);
                if (row < nrows) {
                    if (FUSE_H1) {
                        float2 ag = *(const float2*)(d_agg1 + row * 64 + k0 + k);
                        float2 yv = *(const float2*)(d_yr + row * 64 + k0 + k);
                        v.x = fmaxf(ag.x * inv + yv.x, 0.f);
                        v.y = fmaxf(ag.y * inv + yv.y, 0.f);
                    } else {
                        v = *(const float2*)(A + (long)row * K + k0 + k);
                    }
                }
                int pp = ((jg >> 2) & 1) + (jg & 3) * 2 + (jg >> 3) * 8;
                ((u32*)(sAh + r * 48))[pp] = bf2_hi(v.x, v.y);
                ((u32*)(sAl + r * 48))[pp] = bf2_lo(v.x, v.y);
            }
        }
        // ---- fill B chunk: n 0..127 = [W1 col | W2 col], k k0..k0+31 ----
        {
            int n = t >> 1, half = t & 1;
            const float* W = (n < 64) ? W1 : W2;
            int nc = (n < 64) ? n : n - 64;
#pragma unroll
            for (int j = 0; j < 8; j++) {
                int jg = half * 8 + j;
                int k = k0 + 2 * jg;
                float wx = W[k * 64 + nc];
                float wy = W[(k + 1) * 64 + nc];
                int pp = ((jg >> 2) & 1) + (jg & 3) * 2 + (jg >> 3) * 8;
                ((u32*)(sBh + n * 48))[pp] = bf2_hi(wx, wy);
                ((u32*)(sBl + n * 48))[pp] = bf2_lo(wx, wy);
            }
        }
        __syncthreads();

        // ---- 3 split terms x 2 k16 steps x 16 n-tiles ----
#pragma unroll
        for (int term = 0; term < 3; term++) {
            const __nv_bfloat16* As = (term == 1) ? sAl : sAh;
            const __nv_bfloat16* Bs = (term == 2) ? sBl : sBh;
#pragma unroll
            for (int ks = 0; ks < 2; ks++) {
                ull av0 = *(const ull*)(As + (w * 16 + g) * 48 + ks * 16 + tg * 4);
                ull av1 = *(const ull*)(As + (w * 16 + g + 8) * 48 + ks * 16 + tg * 4);
                u32 a0 = (u32)av0, a2 = (u32)(av0 >> 32);
                u32 a1 = (u32)av1, a3 = (u32)(av1 >> 32);
#pragma unroll
                for (int nt = 0; nt < 16; nt++) {
                    ull bv = *(const ull*)(Bs + (nt * 8 + g) * 48 + ks * 16 + tg * 4);
                    mma16816(acc[nt], a0, a1, a2, a3, (u32)bv, (u32)(bv >> 32));
                }
            }
        }
        __syncthreads();
    }

    // ---- store: c0/c1 -> row, c2/c3 -> row+8; col = nt*8 + tg*2 ----
    int r0 = row0 + w * 16 + g;
#pragma unroll
    for (int nt = 0; nt < 16; nt++) {
        int col = nt * 8 + tg * 2;
        if (col < 64) {
            if (r0 < nrows)
                *(float2*)(C1 + (long)r0 * 64 + col) = make_float2(acc[nt][0], acc[nt][1]);
            if (r0 + 8 < nrows)
                *(float2*)(C1 + (long)(r0 + 8) * 64 + col) = make_float2(acc[nt][2], acc[nt][3]);
        } else {
            int c2 = col - 64;
            float2 bb = *(const float2*)(bias + c2);
            if (r0 < nrows)
                *(float2*)(C2 + (long)r0 * 64 + c2) =
                    make_float2(acc[nt][0] + bb.x, acc[nt][1] + bb.y);
            if (r0 + 8 < nrows)
                *(float2*)(C2 + (long)(r0 + 8) * 64 + c2) =
                    make_float2(acc[nt][2] + bb.x, acc[nt][3] + bb.y);
        }
    }
}

// ---------------- conv1 edge scatter (8 edges/warp) -----------------------------
__global__ void scatter1_kernel(const int* __restrict__ ei) {
    int tid = blockIdx.x * blockDim.x + threadIdx.x;
    int w = tid >> 5, lane = tid & 31;
    int e0 = 8 * w + (lane >> 4);
    int j = lane & 15;

    int s0 = ei[e0];
    int s1 = ei[e0 + 2];
    int s2 = ei[e0 + 4];
    int s3 = ei[e0 + 6];
    int dd0 = ei[E1N + e0];
    int dd1 = ei[E1N + e0 + 2];
    int dd2 = ei[E1N + e0 + 4];
    int dd3 = ei[E1N + e0 + 6];

    float4 v0 = ((const float4*)(d_yl + s0 * 64))[j];
    float4 v1 = ((const float4*)(d_yl + s1 * 64))[j];
    float4 v2 = ((const float4*)(d_yl + s2 * 64))[j];
    float4 v3 = ((const float4*)(d_yl + s3 * 64))[j];

    float* p0 = d_agg1 + dd0 * 64 + 4 * j;
    float* p1 = d_agg1 + dd1 * 64 + 4 * j;
    float* p2 = d_agg1 + dd2 * 64 + 4 * j;
    float* p3 = d_agg1 + dd3 * 64 + 4 * j;
    asm volatile("red.global.add.v4.f32 [%0], {%1,%2,%3,%4};"
                 :: "l"(p0), "f"(v0.x), "f"(v0.y), "f"(v0.z), "f"(v0.w) : "memory");
    asm volatile("red.global.add.v4.f32 [%0], {%1,%2,%3,%4};"
                 :: "l"(p1), "f"(v1.x), "f"(v1.y), "f"(v1.z), "f"(v1.w) : "memory");
    asm volatile("red.global.add.v4.f32 [%0], {%1,%2,%3,%4};"
                 :: "l"(p2), "f"(v2.x), "f"(v2.y), "f"(v2.z), "f"(v2.w) : "memory");
    asm volatile("red.global.add.v4.f32 [%0], {%1,%2,%3,%4};"
                 :: "l"(p3), "f"(v3.x), "f"(v3.y), "f"(v3.z), "f"(v3.w) : "memory");
    if (j == 0) {
        atomicAdd(&d_deg1[dd0], 1.0f);
        atomicAdd(&d_deg1[dd1], 1.0f);
        atomicAdd(&d_deg1[dd2], 1.0f);
        atomicAdd(&d_deg1[dd3], 1.0f);
    }
}

// ---------------- slot assignment + bitmap --------------------------------------
__global__ void slot_kernel(const int* __restrict__ targets,
                            const int* __restrict__ regions) {
    int idx = blockIdx.x * blockDim.x + threadIdx.x;
    if (idx >= BGRAPH * (AREG + 1)) return;
    int b = idx / (AREG + 1);
    int j = idx % (AREG + 1);
    int node = (j == AREG) ? targets[b] : regions[b * AREG + j];
    atomicOr(&d_bitmap[b * BMWORDS + (node >> 5)], 1u << (node & 31));
    int* p = &d_slotmap[b * NNODES + node];
    if (atomicCAS(p, -1, -2) == -1) {
        int s = atomicAdd(&d_counter[b], 1);
        atomicExch(p, s);
    }
}

// ---------------- conv2 scatter with smem bitmap filter -------------------------
__global__ void scatter2_kernel(const int* __restrict__ ne) {
    __shared__ unsigned sbm[BMWORDS];
    const int b = blockIdx.y;
    for (int i = threadIdx.x; i < BMWORDS; i += 320)
        sbm[i] = d_bitmap[b * BMWORDS + i];
    __syncthreads();

    const int lane = threadIdx.x & 31;
    const long base = (long)b * 2 * E2N;
    int e0 = blockIdx.x * 1600 + threadIdx.x;
#pragma unroll
    for (int it = 0; it < 5; it++) {
        int e = e0 + it * 320;
        int dst = ne[base + E2N + e];
        bool hit = (sbm[dst >> 5] >> (dst & 31)) & 1u;
        int slot = -1, src = 0;
        if (hit) {
            slot = d_slotmap[b * NNODES + dst];
            src = ne[base + e];
        }
        unsigned mask = __ballot_sync(0xffffffffu, hit);
        while (mask) {
            int bit = __ffs(mask) - 1;
            mask &= mask - 1;
            int es = __shfl_sync(0xffffffffu, src, bit);
            int sl = __shfl_sync(0xffffffffu, slot, bit);
            float2 v = ((const float2*)(d_gl + es * 64))[lane];
            float* p = d_acc2 + (b * SLOTS + sl) * 64 + 2 * lane;
            asm volatile("red.global.add.v2.f32 [%0], {%1,%2};"
                         :: "l"(p), "f"(v.x), "f"(v.y) : "memory");
            if (lane == 0) atomicAdd(&d_deg2[b * SLOTS + sl], 1.0f);
        }
    }
}

// ---------------- u_b = Wo @ t_b , c_b = bo . t_b -------------------------------
__global__ void u_kernel(const int* __restrict__ targets,
                         const float* __restrict__ Wo,
                         const float* __restrict__ bo) {
    int idx = blockIdx.x * blockDim.x + threadIdx.x;
    if (idx >= BGRAPH * HDIM) return;
    int b = idx >> 7;
    int h = idx & 127;
    int node = targets[b];
    int s = d_slotmap[b * NNODES + node];
    int base = (b * SLOTS + s) * 64;
    float inv = 1.f / fmaxf(d_deg2[b * SLOTS + s], 1.f);
    float acc = 0.f, c = 0.f;
#pragma unroll
    for (int d = 0; d < 64; d++) {
        float td = fmaxf(d_acc2[base + d] * inv + d_gr[node * 64 + d], 0.f);
        acc += Wo[h * 64 + d] * td;
        c += bo[d] * td;
    }
    d_u[idx] = acc;
    if (h == 0) d_c[b] = c;
}

// ---------------- final readout -------------------------------------------------
__global__ void final_kernel(const int* __restrict__ regions,
                             const float* __restrict__ Wm,
                             const float* __restrict__ bm,
                             float* __restrict__ q) {
    __shared__ float sWm[64 * 128];
    __shared__ float sreg[8][8][64];
    for (int i = threadIdx.x; i < 64 * 128; i += blockDim.x)
        sWm[i] = Wm[i];
    __syncthreads();

    const int lane = threadIdx.x & 31;
    const int wl = threadIdx.x >> 5;
    const float2 bmp0 = ((const float2*)bm)[lane];
    const float2 bmp1 = ((const float2*)bm)[lane + 32];

    for (int tile = blockIdx.x * 8 + wl; tile < 4000; tile += gridDim.x * 8) {
        int b = tile / 250;
#pragma unroll
        for (int r = 0; r < 8; r++) {
            int p = tile * 8 + r;
            int node = regions[p];
            int s = d_slotmap[b * NNODES + node];
            int base = (b * SLOTS + s) * 64;
            float inv = 1.f / fmaxf(d_deg2[b * SLOTS + s], 1.f);
            float2 a = ((const float2*)(d_acc2 + base))[lane];
            float2 g = ((const float2*)(d_gr + node * 64))[lane];
            sreg[wl][r][2 * lane]     = fmaxf(a.x * inv + g.x, 0.f);
            sreg[wl][r][2 * lane + 1] = fmaxf(a.y * inv + g.y, 0.f);
        }
        __syncwarp();

        ull acc0[8], acc1[8];
#pragma unroll
        for (int r = 0; r < 8; r++) { acc0[r] = 0ull; acc1[r] = 0ull; }

#pragma unroll 8
        for (int d = 0; d < 64; d++) {
            ull w0 = ((const ull*)(sWm + d * 128))[lane];
            ull w1 = ((const ull*)(sWm + d * 128 + 64))[lane];
#pragma unroll
            for (int r = 0; r < 8; r++) {
                float rd = sreg[wl][r][d];
                ull rdp = pack2(rd, rd);
                acc0[r] = ffma2(rdp, w0, acc0[r]);
                acc1[r] = ffma2(rdp, w1, acc1[r]);
            }
        }

        const float2* ubp = (const float2*)(d_u + b * HDIM);
        float2 u0 = ubp[lane];
        float2 u1 = ubp[lane + 32];
        float cb = d_c[b];
#pragma unroll
        for (int r = 0; r < 8; r++) {
            float m0, m1, m2, m3;
            unpack2(acc0[r], m0, m1);
            unpack2(acc1[r], m2, m3);
            float sum = fmaxf(m0 + bmp0.x, 0.f) * u0.x
                      + fmaxf(m1 + bmp0.y, 0.f) * u0.y
                      + fmaxf(m2 + bmp1.x, 0.f) * u1.x
                      + fmaxf(m3 + bmp1.y, 0.f) * u1.y;
#pragma unroll
            for (int o = 16; o > 0; o >>= 1)
                sum += __shfl_down_sync(0xffffffffu, sum, o);
            if (lane == 0) q[tile * 8 + r] = sum + cb;
        }
        __syncwarp();
    }
}

// ---------------- launch ---------------------------------------------------------
extern "C" void kernel_launch(void* const* d_in, const int* in_sizes, int n_in,
                              void* d_out, int out_size) {
    const float* x       = (const float*)d_in[0];
    const int*   ei      = (const int*)  d_in[1];
    const int*   ne      = (const int*)  d_in[2];
    const int*   targets = (const int*)  d_in[3];
    const int*   regions = (const int*)  d_in[4];
    const float* W1l     = (const float*)d_in[5];
    const float* W1r     = (const float*)d_in[6];
    const float* b1      = (const float*)d_in[7];
    const float* W2l     = (const float*)d_in[8];
    const float* W2r     = (const float*)d_in[9];
    const float* b2      = (const float*)d_in[10];
    const float* Wm      = (const float*)d_in[11];
    const float* bm      = (const float*)d_in[12];
    const float* Wo      = (const float*)d_in[13];
    const float* bo      = (const float*)d_in[14];
    float* q = (float*)d_out;

    float *p_yl, *p_yr, *p_gl, *p_gr;
    cudaGetSymbolAddress((void**)&p_yl, d_yl);
    cudaGetSymbolAddress((void**)&p_yr, d_yr);
    cudaGetSymbolAddress((void**)&p_gl, d_gl);
    cudaGetSymbolAddress((void**)&p_gr, d_gr);

    const int gemm_blocks = (NNODES + 127) / 128;   // 391

    // 0. yl = x@W1l ; yr = x@W1r + b1 (HMMA, K=128)
    mma_dual_gemm<FIN, false><<<gemm_blocks, 256>>>(x, W1l, W1r, b1, p_yl, p_yr, NNODES);

    // 1. clear scratch
    clear_kernel<<<(CLR_TOTAL + 255) / 256, 256>>>();

    // 2. conv1 scatter
    {
        int warps = E1N / 8;
        int blocks = (warps * 32 + 255) / 256;
        scatter1_kernel<<<blocks, 256>>>(ei);
    }

    // 3. gl = h1@W2l ; gr = h1@W2r + b2 (HMMA, K=64, h1 fused)  <-- profiled slot
    mma_dual_gemm<DDIM, true><<<gemm_blocks, 256>>>(nullptr, W2l, W2r, b2, p_gl, p_gr, NNODES);

    // 4. slot assignment + bitmap
    slot_kernel<<<(BGRAPH * (AREG + 1) + 255) / 256, 256>>>(targets, regions);

    // 5. conv2 scatter with smem bitmap filter
    {
        dim3 grid(125, BGRAPH);
        scatter2_kernel<<<grid, 320>>>(ne);
    }

    // 6. u_b = Wo @ t_b, c_b
    u_kernel<<<(BGRAPH * HDIM + 255) / 256, 256>>>(targets, Wo, bo);

    // 7. readout
    final_kernel<<<250, 256>>>(regions, Wm, bm, q);
}